// round 1
// baseline (speedup 1.0000x reference)
#include <cuda_runtime.h>

// Problem constants (match reference)
#define N_FEAT_COLS 9
#define CARD 50000
#define EMB 128
#define EDGE_DIM 27

// Precomputed: v[j] = sum_k out_w[k] * edge_w[k][j]   (27 values)
//              g_c  = out_b[0] + sum_k out_w[k] * edge_b[k]
__device__ float g_v[EDGE_DIM];
__device__ float g_c;

__global__ void precompute_v_kernel(const float* __restrict__ edge_w,
                                    const float* __restrict__ edge_b,
                                    const float* __restrict__ out_w,
                                    const float* __restrict__ out_b) {
    int j = threadIdx.x;
    if (j < EDGE_DIM) {
        float s = 0.f;
        #pragma unroll 8
        for (int k = 0; k < EMB; k++) s += out_w[k] * edge_w[k * EDGE_DIM + j];
        g_v[j] = s;
    }
    if (j == EDGE_DIM) {
        float s = out_b[0];
        #pragma unroll 8
        for (int k = 0; k < EMB; k++) s += out_w[k] * edge_b[k];
        g_c = s;
    }
}

__device__ __forceinline__ float4 ld4(const float* __restrict__ p) {
    return *reinterpret_cast<const float4*>(p);
}

// Encode one node's 128-dim embedding; each lane holds 4 contiguous floats.
// rv: this lane's x-row value bundle; base = which*10 offset within rv shuffles.
__device__ __forceinline__ float4 encode_node(int rv, int base, int lane4,
                                              const float* __restrict__ emb_type,
                                              const float* __restrict__ emb_feats) {
    const unsigned FULL = 0xffffffffu;
    int t = __shfl_sync(FULL, rv, base);  // type
    float4 acc = ld4(emb_type + t * EMB + lane4);
    // TYPE_PER_COL = (0,0,0,0,1,2,2,2,2):
    //   t==0 -> cols 0..3, t==1 -> col 4, t==2 -> cols 5..8
    int h0 = (t == 0) ? 0 : (t == 1) ? 4 : 5;
    int nh = (t == 1) ? 1 : 4;
    #pragma unroll 4
    for (int i = 0; i < 4; i++) {
        if (i < nh) {
            int h = h0 + i;
            int f = __shfl_sync(FULL, rv, base + h + 1);
            const float* p = emb_feats + ((long long)h * CARD + f) * EMB + lane4;
            float4 e = ld4(p);
            acc.x += e.x; acc.y += e.y; acc.z += e.z; acc.w += e.w;
        }
    }
    return acc;
}

__global__ __launch_bounds__(256)
void edge_pred_kernel(const int* __restrict__ x,
                      const int* __restrict__ src,
                      const int* __restrict__ dst,
                      const int* __restrict__ neg_dst,
                      const float* __restrict__ msg,
                      const float* __restrict__ emb_type,
                      const float* __restrict__ emb_feats,
                      const float* __restrict__ out_w,
                      float* __restrict__ out,
                      int E) {
    const unsigned FULL = 0xffffffffu;
    int warp = (blockIdx.x * blockDim.x + threadIdx.x) >> 5;
    int lane = threadIdx.x & 31;
    if (warp >= E) return;
    int e = warp;

    int s  = __ldg(src + e);
    int d  = __ldg(dst + e);
    int nd = __ldg(neg_dst + e);

    // Lanes 0..29 cooperatively load the three 10-int x rows in one LDG.
    int which = lane / 10;          // 0:src 1:dst 2:neg
    int off   = lane - which * 10;
    int nid   = (which == 0) ? s : (which == 1) ? d : nd;
    int rv = 0;
    if (lane < 30) rv = __ldg(x + (long long)nid * 10 + off);

    int lane4 = lane * 4;
    float4 hs = encode_node(rv, 0,  lane4, emb_type, emb_feats);
    float4 hd = encode_node(rv, 10, lane4, emb_type, emb_feats);
    float4 hn = encode_node(rv, 20, lane4, emb_type, emb_feats);

    float4 ow = ld4(out_w + lane4);

    float pp = fmaxf(hs.x + hd.x, 0.f) * ow.x
             + fmaxf(hs.y + hd.y, 0.f) * ow.y
             + fmaxf(hs.z + hd.z, 0.f) * ow.z
             + fmaxf(hs.w + hd.w, 0.f) * ow.w;
    float np = fmaxf(hs.x + hn.x, 0.f) * ow.x
             + fmaxf(hs.y + hn.y, 0.f) * ow.y
             + fmaxf(hs.z + hn.z, 0.f) * ow.z
             + fmaxf(hs.w + hn.w, 0.f) * ow.w;

    // msg dot with precomputed v (folded into both partials)
    float m = 0.f;
    if (lane < EDGE_DIM)
        m = __ldg(msg + (long long)e * EDGE_DIM + lane) * g_v[lane];
    pp += m;
    np += m;

    #pragma unroll
    for (int o = 16; o > 0; o >>= 1) {
        pp += __shfl_xor_sync(FULL, pp, o);
        np += __shfl_xor_sync(FULL, np, o);
    }

    if (lane == 0) {
        float c = g_c;
        out[e]     = pp + c;   // pos
        out[E + e] = np + c;   // neg
    }
}

extern "C" void kernel_launch(void* const* d_in, const int* in_sizes, int n_in,
                              void* d_out, int out_size) {
    const int*   x        = (const int*)  d_in[0];
    const int*   src      = (const int*)  d_in[1];
    const int*   dst      = (const int*)  d_in[2];
    const int*   neg_dst  = (const int*)  d_in[3];
    const float* msg      = (const float*)d_in[4];
    const float* emb_type = (const float*)d_in[5];
    const float* emb_feats= (const float*)d_in[6];
    const float* edge_w   = (const float*)d_in[7];
    const float* edge_b   = (const float*)d_in[8];
    const float* out_w    = (const float*)d_in[9];
    const float* out_b    = (const float*)d_in[10];
    float* out = (float*)d_out;

    int E = in_sizes[1];

    precompute_v_kernel<<<1, 32>>>(edge_w, edge_b, out_w, out_b);

    int threads = 256;
    int warps_per_block = threads / 32;
    int blocks = (E + warps_per_block - 1) / warps_per_block;
    edge_pred_kernel<<<blocks, threads>>>(x, src, dst, neg_dst, msg,
                                          emb_type, emb_feats, out_w, out, E);
}

// round 3
// speedup vs baseline: 1.0350x; 1.0350x over previous
#include <cuda_runtime.h>

// Problem constants (match reference)
#define N_FEAT_COLS 9
#define CARD 50000
#define EMB 128
#define EDGE_DIM 27

// Precomputed: v[j] = sum_k out_w[k] * edge_w[k][j]   (27 values)
//              g_c  = out_b[0] + sum_k out_w[k] * edge_b[k]
__device__ float g_v[EDGE_DIM];
__device__ float g_c;

__global__ void precompute_v_kernel(const float* __restrict__ edge_w,
                                    const float* __restrict__ edge_b,
                                    const float* __restrict__ out_w,
                                    const float* __restrict__ out_b) {
    int j = threadIdx.x;
    if (j < EDGE_DIM) {
        float s = 0.f;
        #pragma unroll 8
        for (int k = 0; k < EMB; k++) s += out_w[k] * edge_w[k * EDGE_DIM + j];
        g_v[j] = s;
    }
    if (j == EDGE_DIM) {
        float s = out_b[0];
        #pragma unroll 8
        for (int k = 0; k < EMB; k++) s += out_w[k] * edge_b[k];
        g_c = s;
    }
}

// Hot-table gather: evict_last via cache-policy form (the inline qualifier
// form is rejected by ptxas for .v4.f32 on sm_103).
__device__ __forceinline__ float4 ld4_hot(const float* __restrict__ p) {
    float4 v;
    asm("{\n\t"
        ".reg .b64 pol;\n\t"
        "createpolicy.fractional.L2::evict_last.b64 pol, 1.0;\n\t"
        "ld.global.nc.L2::cache_hint.v4.f32 {%0,%1,%2,%3}, [%4], pol;\n\t"
        "}"
        : "=f"(v.x), "=f"(v.y), "=f"(v.z), "=f"(v.w) : "l"(p));
    return v;
}
__device__ __forceinline__ float4 ld4(const float* __restrict__ p) {
    return *reinterpret_cast<const float4*>(p);
}

// Encode one node's 128-dim embedding; each lane holds 4 contiguous floats.
// rv: this lane's x-row value bundle; base = which*10 offset within rv shuffles.
__device__ __forceinline__ float4 encode_node(int rv, int base, int lane4,
                                              const float* __restrict__ emb_type,
                                              const float* __restrict__ emb_feats) {
    const unsigned FULL = 0xffffffffu;
    int t = __shfl_sync(FULL, rv, base);  // type
    float4 acc = ld4(emb_type + t * EMB + lane4);   // tiny table, always resident
    // TYPE_PER_COL = (0,0,0,0,1,2,2,2,2):
    //   t==0 -> cols 0..3, t==1 -> col 4, t==2 -> cols 5..8
    int h0 = (t == 0) ? 0 : (t == 1) ? 4 : 5;
    int nh = (t == 1) ? 1 : 4;
    #pragma unroll 4
    for (int i = 0; i < 4; i++) {
        if (i < nh) {
            int h = h0 + i;
            int f = __shfl_sync(FULL, rv, base + h + 1);
            const float* p = emb_feats + ((long long)h * CARD + f) * EMB + lane4;
            float4 e = ld4_hot(p);
            acc.x += e.x; acc.y += e.y; acc.z += e.z; acc.w += e.w;
        }
    }
    return acc;
}

__global__ __launch_bounds__(256)
void edge_pred_kernel(const int* __restrict__ x,
                      const int* __restrict__ src,
                      const int* __restrict__ dst,
                      const int* __restrict__ neg_dst,
                      const float* __restrict__ msg,
                      const float* __restrict__ emb_type,
                      const float* __restrict__ emb_feats,
                      const float* __restrict__ out_w,
                      float* __restrict__ out,
                      int E) {
    const unsigned FULL = 0xffffffffu;
    int warp = (blockIdx.x * blockDim.x + threadIdx.x) >> 5;
    int lane = threadIdx.x & 31;
    if (warp >= E) return;
    int e = warp;

    // Streaming loads: .cs (evict-first behavior), don't pollute L2.
    int s  = __ldcs(src + e);
    int d  = __ldcs(dst + e);
    int nd = __ldcs(neg_dst + e);

    // Lanes 0..29 cooperatively load the three 10-int x rows in one LDG.
    int which = lane / 10;          // 0:src 1:dst 2:neg
    int off   = lane - which * 10;
    int nid   = (which == 0) ? s : (which == 1) ? d : nd;
    int rv = 0;
    if (lane < 30) rv = __ldcs(x + (long long)nid * 10 + off);

    // msg dot with precomputed v (streaming, issue early for MLP)
    float m = 0.f;
    if (lane < EDGE_DIM)
        m = __ldcs(msg + (long long)e * EDGE_DIM + lane) * g_v[lane];

    int lane4 = lane * 4;
    float4 hs = encode_node(rv, 0,  lane4, emb_type, emb_feats);
    float4 hd = encode_node(rv, 10, lane4, emb_type, emb_feats);
    float4 hn = encode_node(rv, 20, lane4, emb_type, emb_feats);

    float4 ow = ld4(out_w + lane4);

    float pp = fmaxf(hs.x + hd.x, 0.f) * ow.x
             + fmaxf(hs.y + hd.y, 0.f) * ow.y
             + fmaxf(hs.z + hd.z, 0.f) * ow.z
             + fmaxf(hs.w + hd.w, 0.f) * ow.w;
    float np = fmaxf(hs.x + hn.x, 0.f) * ow.x
             + fmaxf(hs.y + hn.y, 0.f) * ow.y
             + fmaxf(hs.z + hn.z, 0.f) * ow.z
             + fmaxf(hs.w + hn.w, 0.f) * ow.w;

    pp += m;
    np += m;

    #pragma unroll
    for (int o = 16; o > 0; o >>= 1) {
        pp += __shfl_xor_sync(FULL, pp, o);
        np += __shfl_xor_sync(FULL, np, o);
    }

    if (lane == 0) {
        float c = g_c;
        out[e]     = pp + c;   // pos
        out[E + e] = np + c;   // neg
    }
}

extern "C" void kernel_launch(void* const* d_in, const int* in_sizes, int n_in,
                              void* d_out, int out_size) {
    const int*   x        = (const int*)  d_in[0];
    const int*   src      = (const int*)  d_in[1];
    const int*   dst      = (const int*)  d_in[2];
    const int*   neg_dst  = (const int*)  d_in[3];
    const float* msg      = (const float*)d_in[4];
    const float* emb_type = (const float*)d_in[5];
    const float* emb_feats= (const float*)d_in[6];
    const float* edge_w   = (const float*)d_in[7];
    const float* edge_b   = (const float*)d_in[8];
    const float* out_w    = (const float*)d_in[9];
    const float* out_b    = (const float*)d_in[10];
    float* out = (float*)d_out;

    int E = in_sizes[1];

    precompute_v_kernel<<<1, 32>>>(edge_w, edge_b, out_w, out_b);

    int threads = 256;
    int warps_per_block = threads / 32;
    int blocks = (E + warps_per_block - 1) / warps_per_block;
    edge_pred_kernel<<<blocks, threads>>>(x, src, dst, neg_dst, msg,
                                          emb_type, emb_feats, out_w, out, E);
}